// round 3
// baseline (speedup 1.0000x reference)
#include <cuda_runtime.h>

// WaveLetPooling: input (8, 512, 512, 64) fp32 NHWC.
// Output: [ll | lh | hl | hh], each (8, 256, 256, 64), concatenated in d_out.
// One output position (one float4 of channels) per thread — the highest-
// occupancy shape measured. Butterfly-factored Haar (8 adds + 4 muls per
// float4 instead of 16 FMAs). Streaming stores (evict-first), default loads.

#define N_  8u
#define H_  512u
#define W_  512u
#define C_  64u
#define HO  (H_/2u)       // 256
#define WO  (W_/2u)       // 256
#define C4  (C_/4u)       // 16 float4 per position
#define Q4  (N_*HO*WO*C4) // float4 per quadrant = 8,388,608

__device__ __forceinline__ float4 f4add(const float4& x, const float4& y) {
    return make_float4(x.x + y.x, x.y + y.y, x.z + y.z, x.w + y.w);
}
__device__ __forceinline__ float4 f4sub(const float4& x, const float4& y) {
    return make_float4(x.x - y.x, x.y - y.y, x.z - y.z, x.w - y.w);
}
__device__ __forceinline__ float4 f4half(const float4& x) {
    return make_float4(0.5f * x.x, 0.5f * x.y, 0.5f * x.z, 0.5f * x.w);
}

__global__ __launch_bounds__(512) void wavelet_pool_kernel(
    const float4* __restrict__ in, float4* __restrict__ out)
{
    unsigned tid = blockIdx.x * blockDim.x + threadIdx.x;
    // tid -> (n, ho, wo, c4)
    unsigned c4 = tid & 15u;
    unsigned wo = (tid >> 4) & 255u;
    unsigned ho = (tid >> 12) & 255u;
    unsigned n  = tid >> 20;

    unsigned ibase = ((n * H_ + 2u * ho) * W_ + 2u * wo) * C4 + c4;
    const unsigned ROW4 = W_ * C4;  // 8192

    float4 a = in[ibase];
    float4 b = in[ibase + C4];
    float4 c = in[ibase + ROW4];
    float4 d = in[ibase + ROW4 + C4];

    // butterfly: s0=a+b, d0=b-a, s1=c+d, d1=d-c
    float4 s0 = f4add(a, b);
    float4 d0 = f4sub(b, a);
    float4 s1 = f4add(c, d);
    float4 d1 = f4sub(d, c);

    float4 ll = f4half(f4add(s0, s1));  //  a+b+c+d
    float4 lh = f4half(f4add(d0, d1));  // -a+b-c+d
    float4 hl = f4half(f4sub(s1, s0));  // -a-b+c+d
    float4 hh = f4half(f4sub(d1, d0));  //  a-b-c+d

    unsigned o = ((n * HO + ho) * WO + wo) * C4 + c4;
    __stcs(out + o,           ll);
    __stcs(out + o + Q4,      lh);
    __stcs(out + o + 2u*Q4,   hl);
    __stcs(out + o + 3u*Q4,   hh);
}

extern "C" void kernel_launch(void* const* d_in, const int* in_sizes, int n_in,
                              void* d_out, int out_size)
{
    const float4* in  = (const float4*)d_in[0];
    float4*       out = (float4*)d_out;

    const unsigned total = Q4;             // 8,388,608 threads
    const unsigned block = 512;
    const unsigned grid  = total / block;  // 16384
    wavelet_pool_kernel<<<grid, block>>>(in, out);
}